// round 10
// baseline (speedup 1.0000x reference)
#include <cuda_runtime.h>
#include <cuda_fp16.h>
#include <cstdint>

#define B_    4
#define N_    16384
#define C_    64
#define K_    16
#define O_    64
#define RTOT  (B_ * N_)          // 65536 rows
#define TOTSAMP 1048576.0f
#define BN_EPS 1e-5f

__device__ __align__(16) float  g_u [RTOT * O_];   // fp32
__device__ __align__(16) __half g_vh[RTOT * O_];   // fp16 gather operand
__device__ __align__(16) float  g_mx[RTOT * O_];   // u + max_k v
__device__ __align__(16) float  g_mn[RTOT * O_];   // u + min_k v
__device__ float g_sum[O_];
__device__ float g_sq[O_];
__device__ __align__(16) float g_scale[O_];
__device__ __align__(16) float g_shift[O_];
__device__ int   g_neg;
// fragment-ordered split weights: [ks(8)][tcol(16)][lane(32)] float2
__device__ __align__(16) float2 g_Bh[8 * 16 * 32];
__device__ __align__(16) float2 g_Bl[8 * 16 * 32];

// ---------------------------------------------------------------------------
// tf32 helpers
// ---------------------------------------------------------------------------
__device__ __forceinline__ float tf32f(float a) {
    uint32_t u;
    asm("cvt.rna.tf32.f32 %0, %1;" : "=r"(u) : "f"(a));
    return __uint_as_float(u);
}
__device__ __forceinline__ void mma_tf32(float d[4], const uint32_t a[4],
                                         const uint32_t b0, const uint32_t b1) {
    asm volatile(
        "mma.sync.aligned.m16n8k8.row.col.f32.tf32.tf32.f32 "
        "{%0,%1,%2,%3}, {%4,%5,%6,%7}, {%8,%9}, {%0,%1,%2,%3};"
        : "+f"(d[0]), "+f"(d[1]), "+f"(d[2]), "+f"(d[3])
        : "r"(a[0]), "r"(a[1]), "r"(a[2]), "r"(a[3]), "r"(b0), "r"(b1));
}

// ---------------------------------------------------------------------------
// K0: pre-split weights + zero stats.
// ---------------------------------------------------------------------------
__global__ void k_prep(const float* __restrict__ w) {
    int i = blockIdx.x * 256 + threadIdx.x;
    if (i < 64) { g_sum[i] = 0.f; g_sq[i] = 0.f; }
    if (i >= 8 * 16 * 32) return;
    int l  = i & 31;
    int t  = (i >> 5) & 15;
    int ks = i >> 9;
    int n = t * 8 + (l >> 2);
    int k = ks * 8 + (l & 3);
    float v0, v1;
    if (n < 64) {
        v0 = w[n * 128 + k]     - w[n * 128 + 64 + k];
        v1 = w[n * 128 + k + 4] - w[n * 128 + 64 + k + 4];
    } else {
        v0 = w[(n - 64) * 128 + 64 + k];
        v1 = w[(n - 64) * 128 + 64 + k + 4];
    }
    float h0 = tf32f(v0), h1 = tf32f(v1);
    g_Bh[i] = make_float2(h0, h1);
    g_Bl[i] = make_float2(tf32f(v0 - h0), tf32f(v1 - h1));
}

// ---------------------------------------------------------------------------
// K1: GEMM (unchanged from R9): u fp32, v fp16.
// ---------------------------------------------------------------------------
#define XPITCH 68
__global__ __launch_bounds__(256, 3) void k_gemm(const float* __restrict__ x) {
    __shared__ float sX[64][XPITCH];

    int tid = threadIdx.x;
    int lane = tid & 31, wid = tid >> 5;
    int rg = wid & 3, cg = wid >> 2;

    int rowBase = blockIdx.x * 64;
    const float4* x4 = (const float4*)(x + (size_t)rowBase * 64);
    for (int i = tid; i < 64 * 16; i += 256) {
        int r = i >> 4, c4 = i & 15;
        float4 v = x4[i];
        float* p = &sX[r][c4 * 4];
        p[0] = v.x; p[1] = v.y; p[2] = v.z; p[3] = v.w;
    }
    __syncthreads();

    float acc[8][4] = {};
    int arow = rg * 16 + (lane >> 2);
    int acol = lane & 3;
    const float2* bhBase = g_Bh + cg * 8 * 32 + lane;
    const float2* blBase = g_Bl + cg * 8 * 32 + lane;

#pragma unroll
    for (int ks = 0; ks < 8; ks++) {
        uint32_t ah[4], al[4];
        {
            float x0 = sX[arow][acol + ks * 8];
            float x1 = sX[arow + 8][acol + ks * 8];
            float x2 = sX[arow][acol + 4 + ks * 8];
            float x3 = sX[arow + 8][acol + 4 + ks * 8];
            float h0 = tf32f(x0), h1 = tf32f(x1), h2 = tf32f(x2), h3 = tf32f(x3);
            ah[0] = __float_as_uint(h0); al[0] = __float_as_uint(tf32f(x0 - h0));
            ah[1] = __float_as_uint(h1); al[1] = __float_as_uint(tf32f(x1 - h1));
            ah[2] = __float_as_uint(h2); al[2] = __float_as_uint(tf32f(x2 - h2));
            ah[3] = __float_as_uint(h3); al[3] = __float_as_uint(tf32f(x3 - h3));
        }
        const float2* bh = bhBase + ks * 16 * 32;
        const float2* bl = blBase + ks * 16 * 32;
#pragma unroll
        for (int t = 0; t < 8; t++) {
            float2 h = __ldg(bh + t * 32);
            float2 l = __ldg(bl + t * 32);
            uint32_t b0 = __float_as_uint(h.x), b1 = __float_as_uint(h.y);
            uint32_t c0 = __float_as_uint(l.x), c1 = __float_as_uint(l.y);
            mma_tf32(acc[t], ah, b0, b1);
            mma_tf32(acc[t], ah, c0, c1);
            mma_tf32(acc[t], al, b0, b1);
        }
    }

    int row = rowBase + rg * 16 + (lane >> 2);
    int col = (lane & 3) * 2;
    if (cg == 0) {
#pragma unroll
        for (int t = 0; t < 8; t++) {
            *(float2*)(g_u + (size_t)row * 64 + t * 8 + col) =
                make_float2(acc[t][0], acc[t][1]);
            *(float2*)(g_u + (size_t)(row + 8) * 64 + t * 8 + col) =
                make_float2(acc[t][2], acc[t][3]);
        }
    } else {
#pragma unroll
        for (int t = 0; t < 8; t++) {
            *(__half2*)(g_vh + (size_t)row * 64 + t * 8 + col) =
                __floats2half2_rn(acc[t][0], acc[t][1]);
            *(__half2*)(g_vh + (size_t)(row + 8) * 64 + t * 8 + col) =
                __floats2half2_rn(acc[t][2], acc[t][3]);
        }
    }
}

// ---------------------------------------------------------------------------
// K2: gather, LDG.128 edition. lane = (q = lane>>3, c8 = lane&7):
// lane handles neighbors k in {q, q+4, q+8, q+12} for channels [c8*8, c8*8+8).
// Per point: 4 idx LDG + 4 v LDG.128 + 2 u LDG.128 (was 19 LDG-class).
// Stats are per-lane linear folds (no cross-lane reduce per point);
// only mx/mn need 2 shfl-xor rounds.
// ---------------------------------------------------------------------------
__device__ __forceinline__ __half2 h2shfl(__half2 v, int m) {
    uint32_t u = __shfl_xor_sync(0xffffffffu, *(uint32_t*)&v, m);
    return *(__half2*)&u;
}

__global__ __launch_bounds__(256) void k_gather(const int* __restrict__ idx) {
    int tid  = threadIdx.x;
    int lane = tid & 31;
    int q    = lane >> 3;
    int c8   = lane & 7;
    int warpId = blockIdx.x * 8 + (tid >> 5);
    int pbase  = warpId * 16;
    int b = pbase >> 14;
    const uint4* vb = (const uint4*)(g_vh + (size_t)b * N_ * O_);  // 8 uint4/row

    float cs1[8] = {}, cs2[8] = {};

    for (int p = 0; p < 16; ++p) {
        int point = pbase + p;
        const int* ip = idx + (size_t)point * K_;

        int j0 = __ldg(&ip[q]);
        int j1 = __ldg(&ip[q + 4]);
        int j2 = __ldg(&ip[q + 8]);
        int j3 = __ldg(&ip[q + 12]);

        uint4 r0 = __ldg(vb + (size_t)j0 * 8 + c8);
        uint4 r1 = __ldg(vb + (size_t)j1 * 8 + c8);
        uint4 r2 = __ldg(vb + (size_t)j2 * 8 + c8);
        uint4 r3 = __ldg(vb + (size_t)j3 * 8 + c8);

        const float4* up = (const float4*)(g_u + (size_t)point * O_);
        float4 ua = __ldg(up + c8 * 2);
        float4 ub = __ldg(up + c8 * 2 + 1);

        __half2 h0 = *(__half2*)&r0.x, h1 = *(__half2*)&r0.y,
                h2 = *(__half2*)&r0.z, h3 = *(__half2*)&r0.w;
        __half2 mx0 = h0, mx1 = h1, mx2 = h2, mx3 = h3;
        __half2 mn0 = h0, mn1 = h1, mn2 = h2, mn3 = h3;
        __half2 s10 = h0, s11 = h1, s12 = h2, s13 = h3;
        __half2 s20 = __hmul2(h0, h0), s21 = __hmul2(h1, h1),
                s22 = __hmul2(h2, h2), s23 = __hmul2(h3, h3);
#define PROC(R)                                                              \
        { __half2 a0 = *(__half2*)&R.x, a1 = *(__half2*)&R.y,                \
                  a2 = *(__half2*)&R.z, a3 = *(__half2*)&R.w;                \
          mx0 = __hmax2(mx0, a0); mn0 = __hmin2(mn0, a0);                    \
          s10 = __hadd2(s10, a0); s20 = __hfma2(a0, a0, s20);                \
          mx1 = __hmax2(mx1, a1); mn1 = __hmin2(mn1, a1);                    \
          s11 = __hadd2(s11, a1); s21 = __hfma2(a1, a1, s21);                \
          mx2 = __hmax2(mx2, a2); mn2 = __hmin2(mn2, a2);                    \
          s12 = __hadd2(s12, a2); s22 = __hfma2(a2, a2, s22);                \
          mx3 = __hmax2(mx3, a3); mn3 = __hmin2(mn3, a3);                    \
          s13 = __hadd2(s13, a3); s23 = __hfma2(a3, a3, s23); }
        PROC(r1); PROC(r2); PROC(r3);
#undef PROC

        // per-lane stats fold: this lane covered 4 k's for its 8 channels.
        float2 t0 = __half22float2(s10), t1 = __half22float2(s11),
               t2 = __half22float2(s12), t3 = __half22float2(s13);
        float2 w0 = __half22float2(s20), w1 = __half22float2(s21),
               w2 = __half22float2(s22), w3 = __half22float2(s23);
        float uu[8] = {ua.x, ua.y, ua.z, ua.w, ub.x, ub.y, ub.z, ub.w};
        float s1f[8] = {t0.x, t0.y, t1.x, t1.y, t2.x, t2.y, t3.x, t3.y};
        float s2f[8] = {w0.x, w0.y, w1.x, w1.y, w2.x, w2.y, w3.x, w3.y};
#pragma unroll
        for (int i = 0; i < 8; i++) {
            cs1[i] += fmaf(4.f, uu[i], s1f[i]);
            cs2[i] += fmaf(uu[i], fmaf(4.f, uu[i], 2.f * s1f[i]), s2f[i]);
        }

        // reduce mx/mn across q-groups (lanes with same c8)
        mx0 = __hmax2(mx0, h2shfl(mx0, 16)); mx0 = __hmax2(mx0, h2shfl(mx0, 8));
        mx1 = __hmax2(mx1, h2shfl(mx1, 16)); mx1 = __hmax2(mx1, h2shfl(mx1, 8));
        mx2 = __hmax2(mx2, h2shfl(mx2, 16)); mx2 = __hmax2(mx2, h2shfl(mx2, 8));
        mx3 = __hmax2(mx3, h2shfl(mx3, 16)); mx3 = __hmax2(mx3, h2shfl(mx3, 8));
        mn0 = __hmin2(mn0, h2shfl(mn0, 16)); mn0 = __hmin2(mn0, h2shfl(mn0, 8));
        mn1 = __hmin2(mn1, h2shfl(mn1, 16)); mn1 = __hmin2(mn1, h2shfl(mn1, 8));
        mn2 = __hmin2(mn2, h2shfl(mn2, 16)); mn2 = __hmin2(mn2, h2shfl(mn2, 8));
        mn3 = __hmin2(mn3, h2shfl(mn3, 16)); mn3 = __hmin2(mn3, h2shfl(mn3, 8));

        if (lane < 16) {
            int qp = lane >> 3;          // 0 or 1: which float4 of the c8 pair
            float2 a0 = __half22float2(qp ? mx2 : mx0);
            float2 a1 = __half22float2(qp ? mx3 : mx1);
            float2 b0 = __half22float2(qp ? mn2 : mn0);
            float2 b1 = __half22float2(qp ? mn3 : mn1);
            float4 uq = qp ? ub : ua;
            float4* pmx = (float4*)(g_mx + (size_t)point * O_) + c8 * 2 + qp;
            float4* pmn = (float4*)(g_mn + (size_t)point * O_) + c8 * 2 + qp;
            *pmx = make_float4(uq.x + a0.x, uq.y + a0.y, uq.z + a1.x, uq.w + a1.y);
            *pmn = make_float4(uq.x + b0.x, uq.y + b0.y, uq.z + b1.x, uq.w + b1.y);
        }
    }

    __shared__ float ssum[O_], ssq[O_];
    if (tid < O_) { ssum[tid] = 0.f; ssq[tid] = 0.f; }
    __syncthreads();
#pragma unroll
    for (int i = 0; i < 8; i++) {
        atomicAdd(&ssum[c8 * 8 + i], cs1[i]);
        atomicAdd(&ssq[c8 * 8 + i],  cs2[i]);
    }
    __syncthreads();
    if (tid < O_) {
        atomicAdd(&g_sum[tid], ssum[tid]);
        atomicAdd(&g_sq[tid],  ssq[tid]);
    }
}

// ---------------------------------------------------------------------------
// K3a: one tiny block computes the BN affine.
// ---------------------------------------------------------------------------
__global__ void k_stats(const float* __restrict__ gamma,
                        const float* __restrict__ beta) {
    int o = threadIdx.x;
    if (o == 0) g_neg = 0;
    __syncthreads();
    if (o < O_) {
        float inv  = 1.0f / TOTSAMP;
        float mean = g_sum[o] * inv;
        float var  = g_sq[o] * inv - mean * mean;
        float s    = rsqrtf(var + BN_EPS) * gamma[o];
        g_scale[o] = s;
        g_shift[o] = beta[o] - mean * s;
        if (s < 0.f) atomicOr(&g_neg, 1);
    }
}

// ---------------------------------------------------------------------------
// K3b: pure-stream epilogue: out = relu(m*scale + shift).
// ---------------------------------------------------------------------------
__global__ __launch_bounds__(256) void k_out(float* __restrict__ out) {
    size_t i4 = (size_t)blockIdx.x * 256 + threadIdx.x;
    int o4 = (int)(i4 & 15);
    float4 s4 = __ldg((const float4*)g_scale + o4);
    float4 b4 = __ldg((const float4*)g_shift + o4);

    float4 m;
    if (!__ldg(&g_neg)) {
        m = __ldg((const float4*)g_mx + i4);
    } else {
        float4 a = __ldg((const float4*)g_mx + i4);
        float4 c = __ldg((const float4*)g_mn + i4);
        m.x = (s4.x >= 0.f) ? a.x : c.x;
        m.y = (s4.y >= 0.f) ? a.y : c.y;
        m.z = (s4.z >= 0.f) ? a.z : c.z;
        m.w = (s4.w >= 0.f) ? a.w : c.w;
    }
    float4 r;
    r.x = fmaxf(fmaf(m.x, s4.x, b4.x), 0.f);
    r.y = fmaxf(fmaf(m.y, s4.y, b4.y), 0.f);
    r.z = fmaxf(fmaf(m.z, s4.z, b4.z), 0.f);
    r.w = fmaxf(fmaf(m.w, s4.w, b4.w), 0.f);
    ((float4*)out)[i4] = r;
}

extern "C" void kernel_launch(void* const* d_in, const int* in_sizes, int n_in,
                              void* d_out, int out_size) {
    const float* x     = (const float*)d_in[0];
    const int*   idx   = (const int*)  d_in[1];
    const float* w     = (const float*)d_in[2];
    const float* gamma = (const float*)d_in[3];
    const float* beta  = (const float*)d_in[4];
    float* out = (float*)d_out;

    k_prep  <<<16, 256>>>(w);
    k_gemm  <<<RTOT / 64, 256>>>(x);
    k_gather<<<RTOT / (8 * 16), 256>>>(idx);
    k_stats <<<1, 64>>>(gamma, beta);
    k_out   <<<(RTOT * O_ / 4) / 256, 256>>>(out);
}

// round 11
// speedup vs baseline: 1.2463x; 1.2463x over previous
#include <cuda_runtime.h>
#include <cuda_fp16.h>
#include <cstdint>

#define B_    4
#define N_    16384
#define C_    64
#define K_    16
#define O_    64
#define RTOT  (B_ * N_)          // 65536 rows
#define TOTSAMP 1048576.0f
#define BN_EPS 1e-5f

__device__ __align__(16) float  g_u [RTOT * O_];   // fp32
__device__ __align__(16) __half g_vh[RTOT * O_];   // fp16 gather operand
__device__ __align__(16) float  g_mx[RTOT * O_];   // u + max_k v
__device__ __align__(16) float  g_mn[RTOT * O_];   // u + min_k v
__device__ float g_sum[O_];
__device__ float g_sq[O_];
__device__ int   g_gneg;                            // any(gamma < 0)
// fragment-ordered split weights: [ks(8)][tcol(16)][lane(32)] float2
__device__ __align__(16) float2 g_Bh[8 * 16 * 32];
__device__ __align__(16) float2 g_Bl[8 * 16 * 32];

// ---------------------------------------------------------------------------
// tf32 helpers
// ---------------------------------------------------------------------------
__device__ __forceinline__ float tf32f(float a) {
    uint32_t u;
    asm("cvt.rna.tf32.f32 %0, %1;" : "=r"(u) : "f"(a));
    return __uint_as_float(u);
}
__device__ __forceinline__ void mma_tf32(float d[4], const uint32_t a[4],
                                         const uint32_t b0, const uint32_t b1) {
    asm volatile(
        "mma.sync.aligned.m16n8k8.row.col.f32.tf32.tf32.f32 "
        "{%0,%1,%2,%3}, {%4,%5,%6,%7}, {%8,%9}, {%0,%1,%2,%3};"
        : "+f"(d[0]), "+f"(d[1]), "+f"(d[2]), "+f"(d[3])
        : "r"(a[0]), "r"(a[1]), "r"(a[2]), "r"(a[3]), "r"(b0), "r"(b1));
}

// ---------------------------------------------------------------------------
// K0: pre-split weights + zero stats + gamma sign flag.
// ---------------------------------------------------------------------------
__global__ void k_prep(const float* __restrict__ w,
                       const float* __restrict__ gamma) {
    int i = blockIdx.x * 256 + threadIdx.x;
    if (i < 64) { g_sum[i] = 0.f; g_sq[i] = 0.f; }
    if (i == 64) {                       // one thread: scan gamma signs
        int neg = 0;
        for (int o = 0; o < O_; o++) neg |= (gamma[o] < 0.f);
        g_gneg = neg;
    }
    if (i >= 8 * 16 * 32) return;
    int l  = i & 31;
    int t  = (i >> 5) & 15;
    int ks = i >> 9;
    int n = t * 8 + (l >> 2);
    int k = ks * 8 + (l & 3);
    float v0, v1;
    if (n < 64) {
        v0 = w[n * 128 + k]     - w[n * 128 + 64 + k];
        v1 = w[n * 128 + k + 4] - w[n * 128 + 64 + k + 4];
    } else {
        v0 = w[(n - 64) * 128 + 64 + k];
        v1 = w[(n - 64) * 128 + 64 + k + 4];
    }
    float h0 = tf32f(v0), h1 = tf32f(v1);
    g_Bh[i] = make_float2(h0, h1);
    g_Bl[i] = make_float2(tf32f(v0 - h0), tf32f(v1 - h1));
}

// ---------------------------------------------------------------------------
// K1: GEMM (R9): u fp32, v fp16.
// ---------------------------------------------------------------------------
#define XPITCH 68
__global__ __launch_bounds__(256, 3) void k_gemm(const float* __restrict__ x) {
    __shared__ float sX[64][XPITCH];

    int tid = threadIdx.x;
    int lane = tid & 31, wid = tid >> 5;
    int rg = wid & 3, cg = wid >> 2;

    int rowBase = blockIdx.x * 64;
    const float4* x4 = (const float4*)(x + (size_t)rowBase * 64);
    for (int i = tid; i < 64 * 16; i += 256) {
        int r = i >> 4, c4 = i & 15;
        float4 v = x4[i];
        float* p = &sX[r][c4 * 4];
        p[0] = v.x; p[1] = v.y; p[2] = v.z; p[3] = v.w;
    }
    __syncthreads();

    float acc[8][4] = {};
    int arow = rg * 16 + (lane >> 2);
    int acol = lane & 3;
    const float2* bhBase = g_Bh + cg * 8 * 32 + lane;
    const float2* blBase = g_Bl + cg * 8 * 32 + lane;

#pragma unroll
    for (int ks = 0; ks < 8; ks++) {
        uint32_t ah[4], al[4];
        {
            float x0 = sX[arow][acol + ks * 8];
            float x1 = sX[arow + 8][acol + ks * 8];
            float x2 = sX[arow][acol + 4 + ks * 8];
            float x3 = sX[arow + 8][acol + 4 + ks * 8];
            float h0 = tf32f(x0), h1 = tf32f(x1), h2 = tf32f(x2), h3 = tf32f(x3);
            ah[0] = __float_as_uint(h0); al[0] = __float_as_uint(tf32f(x0 - h0));
            ah[1] = __float_as_uint(h1); al[1] = __float_as_uint(tf32f(x1 - h1));
            ah[2] = __float_as_uint(h2); al[2] = __float_as_uint(tf32f(x2 - h2));
            ah[3] = __float_as_uint(h3); al[3] = __float_as_uint(tf32f(x3 - h3));
        }
        const float2* bh = bhBase + ks * 16 * 32;
        const float2* bl = blBase + ks * 16 * 32;
#pragma unroll
        for (int t = 0; t < 8; t++) {
            float2 h = __ldg(bh + t * 32);
            float2 l = __ldg(bl + t * 32);
            uint32_t b0 = __float_as_uint(h.x), b1 = __float_as_uint(h.y);
            uint32_t c0 = __float_as_uint(l.x), c1 = __float_as_uint(l.y);
            mma_tf32(acc[t], ah, b0, b1);
            mma_tf32(acc[t], ah, c0, c1);
            mma_tf32(acc[t], al, b0, b1);
        }
    }

    int row = rowBase + rg * 16 + (lane >> 2);
    int col = (lane & 3) * 2;
    if (cg == 0) {
#pragma unroll
        for (int t = 0; t < 8; t++) {
            *(float2*)(g_u + (size_t)row * 64 + t * 8 + col) =
                make_float2(acc[t][0], acc[t][1]);
            *(float2*)(g_u + (size_t)(row + 8) * 64 + t * 8 + col) =
                make_float2(acc[t][2], acc[t][3]);
        }
    } else {
#pragma unroll
        for (int t = 0; t < 8; t++) {
            *(__half2*)(g_vh + (size_t)row * 64 + t * 8 + col) =
                __floats2half2_rn(acc[t][0], acc[t][1]);
            *(__half2*)(g_vh + (size_t)(row + 8) * 64 + t * 8 + col) =
                __floats2half2_rn(acc[t][2], acc[t][3]);
        }
    }
}

// ---------------------------------------------------------------------------
// K2: gather (R9 layout) + smem-staged idx + optional min-skip.
// One warp per 16 points; half-warp per k-parity; lane owns one uint2
// (4 channels). idx for all 16 points preloaded to smem (2 LDG.128/lane),
// so the per-point chain starts from a 29-cyc LDS, not a ~250-cyc LDG.
// ---------------------------------------------------------------------------
__global__ __launch_bounds__(256) void k_gather(const int* __restrict__ idx) {
    __shared__ int sIdx[8][256];
    __shared__ float ssum[O_], ssq[O_];

    int tid  = threadIdx.x;
    int lane = tid & 31;
    int half = lane >> 4;
    int c4   = lane & 15;
    int w    = tid >> 5;
    int warpId = blockIdx.x * 8 + w;
    int pbase  = warpId * 16;
    int b = pbase >> 14;
    const uint2* vb = (const uint2*)(g_vh + (size_t)b * N_ * O_);

    // stage this warp's 256 idx ints (16 points x 16 k)
    {
        const int4* src = (const int4*)(idx + (size_t)pbase * K_);
        ((int4*)sIdx[w])[lane]      = src[lane];
        ((int4*)sIdx[w])[lane + 32] = src[lane + 32];
    }
    __syncwarp();

    const int gneg = g_gneg;

    float4 cs1 = {0, 0, 0, 0}, cs2 = {0, 0, 0, 0};

    for (int p = 0; p < 16; ++p) {
        int point = pbase + p;
        const int* sip = &sIdx[w][p * 16];

        float4 u = __ldg((const float4*)(g_u + (size_t)point * O_) + c4);

        float4 mx = make_float4(-3.4e38f, -3.4e38f, -3.4e38f, -3.4e38f);
        float4 mn = make_float4( 3.4e38f,  3.4e38f,  3.4e38f,  3.4e38f);
        float4 s1 = {0, 0, 0, 0}, s2 = {0, 0, 0, 0};

        int j[8];
#pragma unroll
        for (int s = 0; s < 8; s++) j[s] = sip[2 * s + half];

        if (!gneg) {
#pragma unroll
            for (int s = 0; s < 8; s++) {
                uint2 raw = __ldg(vb + (size_t)j[s] * 16 + c4);
                float2 v01 = __half22float2(*(__half2*)&raw.x);
                float2 v23 = __half22float2(*(__half2*)&raw.y);
                mx.x = fmaxf(mx.x, v01.x); s1.x += v01.x; s2.x = fmaf(v01.x, v01.x, s2.x);
                mx.y = fmaxf(mx.y, v01.y); s1.y += v01.y; s2.y = fmaf(v01.y, v01.y, s2.y);
                mx.z = fmaxf(mx.z, v23.x); s1.z += v23.x; s2.z = fmaf(v23.x, v23.x, s2.z);
                mx.w = fmaxf(mx.w, v23.y); s1.w += v23.y; s2.w = fmaf(v23.y, v23.y, s2.w);
            }
        } else {
#pragma unroll
            for (int s = 0; s < 8; s++) {
                uint2 raw = __ldg(vb + (size_t)j[s] * 16 + c4);
                float2 v01 = __half22float2(*(__half2*)&raw.x);
                float2 v23 = __half22float2(*(__half2*)&raw.y);
                mx.x = fmaxf(mx.x, v01.x); mn.x = fminf(mn.x, v01.x); s1.x += v01.x; s2.x = fmaf(v01.x, v01.x, s2.x);
                mx.y = fmaxf(mx.y, v01.y); mn.y = fminf(mn.y, v01.y); s1.y += v01.y; s2.y = fmaf(v01.y, v01.y, s2.y);
                mx.z = fmaxf(mx.z, v23.x); mn.z = fminf(mn.z, v23.x); s1.z += v23.x; s2.z = fmaf(v23.x, v23.x, s2.z);
                mx.w = fmaxf(mx.w, v23.y); mn.w = fminf(mn.w, v23.y); s1.w += v23.y; s2.w = fmaf(v23.y, v23.y, s2.w);
            }
        }

        mx.x = fmaxf(mx.x, __shfl_xor_sync(0xffffffffu, mx.x, 16));
        mx.y = fmaxf(mx.y, __shfl_xor_sync(0xffffffffu, mx.y, 16));
        mx.z = fmaxf(mx.z, __shfl_xor_sync(0xffffffffu, mx.z, 16));
        mx.w = fmaxf(mx.w, __shfl_xor_sync(0xffffffffu, mx.w, 16));
        if (half == 0) {
            ((float4*)(g_mx + (size_t)point * O_))[c4] =
                make_float4(u.x + mx.x, u.y + mx.y, u.z + mx.z, u.w + mx.w);
        }
        if (gneg) {
            mn.x = fminf(mn.x, __shfl_xor_sync(0xffffffffu, mn.x, 16));
            mn.y = fminf(mn.y, __shfl_xor_sync(0xffffffffu, mn.y, 16));
            mn.z = fminf(mn.z, __shfl_xor_sync(0xffffffffu, mn.z, 16));
            mn.w = fminf(mn.w, __shfl_xor_sync(0xffffffffu, mn.w, 16));
            if (half == 0) {
                ((float4*)(g_mn + (size_t)point * O_))[c4] =
                    make_float4(u.x + mn.x, u.y + mn.y, u.z + mn.z, u.w + mn.w);
            }
        }

        cs1.x += 8.f * u.x + s1.x;  cs2.x += fmaf(8.f * u.x, u.x, fmaf(2.f * u.x, s1.x, s2.x));
        cs1.y += 8.f * u.y + s1.y;  cs2.y += fmaf(8.f * u.y, u.y, fmaf(2.f * u.y, s1.y, s2.y));
        cs1.z += 8.f * u.z + s1.z;  cs2.z += fmaf(8.f * u.z, u.z, fmaf(2.f * u.z, s1.z, s2.z));
        cs1.w += 8.f * u.w + s1.w;  cs2.w += fmaf(8.f * u.w, u.w, fmaf(2.f * u.w, s1.w, s2.w));
    }

    if (tid < O_) { ssum[tid] = 0.f; ssq[tid] = 0.f; }
    __syncthreads();
    int cb = c4 * 4;
    atomicAdd(&ssum[cb + 0], cs1.x); atomicAdd(&ssq[cb + 0], cs2.x);
    atomicAdd(&ssum[cb + 1], cs1.y); atomicAdd(&ssq[cb + 1], cs2.y);
    atomicAdd(&ssum[cb + 2], cs1.z); atomicAdd(&ssq[cb + 2], cs2.z);
    atomicAdd(&ssum[cb + 3], cs1.w); atomicAdd(&ssq[cb + 3], cs2.w);
    __syncthreads();
    if (tid < O_) {
        atomicAdd(&g_sum[tid], ssum[tid]);
        atomicAdd(&g_sq[tid],  ssq[tid]);
    }
}

// ---------------------------------------------------------------------------
// K3: fused stats + epilogue (R9 version).
// ---------------------------------------------------------------------------
__global__ __launch_bounds__(256) void k_out(const float* __restrict__ gamma,
                                             const float* __restrict__ beta,
                                             float* __restrict__ out) {
    __shared__ __align__(16) float sc[O_];
    __shared__ __align__(16) float sh[O_];
    int tid = threadIdx.x;
    if (tid < O_) {
        float inv  = 1.0f / TOTSAMP;
        float mean = g_sum[tid] * inv;
        float var  = g_sq[tid] * inv - mean * mean;
        float s    = rsqrtf(var + BN_EPS) * gamma[tid];
        sc[tid] = s;
        sh[tid] = beta[tid] - mean * s;
    }
    __syncthreads();

    size_t i4 = (size_t)blockIdx.x * 256 + tid;
    int o4 = (int)(i4 & 15);
    float4 s4 = ((const float4*)sc)[o4];
    float4 b4 = ((const float4*)sh)[o4];

    float4 m;
    if (!g_gneg) {
        m = __ldg((const float4*)g_mx + i4);
    } else {
        float4 a = __ldg((const float4*)g_mx + i4);
        float4 c = __ldg((const float4*)g_mn + i4);
        m.x = (s4.x >= 0.f) ? a.x : c.x;
        m.y = (s4.y >= 0.f) ? a.y : c.y;
        m.z = (s4.z >= 0.f) ? a.z : c.z;
        m.w = (s4.w >= 0.f) ? a.w : c.w;
    }
    float4 r;
    r.x = fmaxf(fmaf(m.x, s4.x, b4.x), 0.f);
    r.y = fmaxf(fmaf(m.y, s4.y, b4.y), 0.f);
    r.z = fmaxf(fmaf(m.z, s4.z, b4.z), 0.f);
    r.w = fmaxf(fmaf(m.w, s4.w, b4.w), 0.f);
    ((float4*)out)[i4] = r;
}

extern "C" void kernel_launch(void* const* d_in, const int* in_sizes, int n_in,
                              void* d_out, int out_size) {
    const float* x     = (const float*)d_in[0];
    const int*   idx   = (const int*)  d_in[1];
    const float* w     = (const float*)d_in[2];
    const float* gamma = (const float*)d_in[3];
    const float* beta  = (const float*)d_in[4];
    float* out = (float*)d_out;

    k_prep  <<<16, 256>>>(w, gamma);
    k_gemm  <<<RTOT / 64, 256>>>(x);
    k_gather<<<RTOT / (8 * 16), 256>>>(idx);
    k_out   <<<(RTOT * O_ / 4) / 256, 256>>>(gamma, beta, out);
}

// round 12
// speedup vs baseline: 1.3521x; 1.0849x over previous
#include <cuda_runtime.h>
#include <cuda_fp16.h>
#include <cstdint>

#define B_    4
#define N_    16384
#define C_    64
#define K_    16
#define O_    64
#define RTOT  (B_ * N_)          // 65536 rows
#define TOTSAMP 1048576.0f
#define BN_EPS 1e-5f

__device__ __align__(16) float  g_u [RTOT * O_];   // fp32
__device__ __align__(16) __half g_vh[RTOT * O_];   // fp16 gather operand
__device__ __align__(16) float  g_mx[RTOT * O_];   // u + max_k v
__device__ __align__(16) float  g_mn[RTOT * O_];   // u + min_k v
__device__ float g_sum[O_];
__device__ float g_sq[O_];
__device__ int   g_gneg;                            // any(gamma < 0)
// fp16 fragment-ordered split weights: [ks(4)][t(16)][lane(32)] uint2 {b0,b1}
__device__ __align__(16) uint2 g_Bh[4 * 16 * 32];
__device__ __align__(16) uint2 g_Bl[4 * 16 * 32];

// ---------------------------------------------------------------------------
// fp16 mma helper (sm_80 baseline PTX)
// ---------------------------------------------------------------------------
__device__ __forceinline__ void mma_f16(float d[4], const uint32_t a[4],
                                        const uint32_t b0, const uint32_t b1) {
    asm volatile(
        "mma.sync.aligned.m16n8k16.row.col.f32.f16.f16.f32 "
        "{%0,%1,%2,%3}, {%4,%5,%6,%7}, {%8,%9}, {%0,%1,%2,%3};"
        : "+f"(d[0]), "+f"(d[1]), "+f"(d[2]), "+f"(d[3])
        : "r"(a[0]), "r"(a[1]), "r"(a[2]), "r"(a[3]), "r"(b0), "r"(b1));
}

__device__ __forceinline__ float wprime(const float* w, int n, int k) {
    return (n < 64) ? (w[n * 128 + k] - w[n * 128 + 64 + k])
                    : w[(n - 64) * 128 + 64 + k];
}

// ---------------------------------------------------------------------------
// K0: pre-split weights into fp16 hi/lo fragment order + zero stats + gneg.
// entry i -> (ks, t, lane): n = t*8 + (l>>2), k = ks*16 + (l&3)*2
// b0 = {W'[n][k], W'[n][k+1]}, b1 = {W'[n][k+8], W'[n][k+9]}
// ---------------------------------------------------------------------------
__global__ void k_prep(const float* __restrict__ w,
                       const float* __restrict__ gamma) {
    int i = blockIdx.x * 256 + threadIdx.x;
    if (i < 64) { g_sum[i] = 0.f; g_sq[i] = 0.f; }
    if (i == 64) {
        int neg = 0;
        for (int o = 0; o < O_; o++) neg |= (gamma[o] < 0.f);
        g_gneg = neg;
    }
    if (i >= 4 * 16 * 32) return;
    int l  = i & 31;
    int t  = (i >> 5) & 15;
    int ks = i >> 9;
    int n = t * 8 + (l >> 2);
    int k = ks * 16 + (l & 3) * 2;

    float v0 = wprime(w, n, k),     v1 = wprime(w, n, k + 1);
    float v2 = wprime(w, n, k + 8), v3 = wprime(w, n, k + 9);

    __half2 h01 = __floats2half2_rn(v0, v1);
    __half2 h23 = __floats2half2_rn(v2, v3);
    float2 f01 = __half22float2(h01);
    float2 f23 = __half22float2(h23);
    __half2 l01 = __floats2half2_rn(v0 - f01.x, v1 - f01.y);
    __half2 l23 = __floats2half2_rn(v2 - f23.x, v3 - f23.y);

    g_Bh[i] = make_uint2(*(uint32_t*)&h01, *(uint32_t*)&h23);
    g_Bl[i] = make_uint2(*(uint32_t*)&l01, *(uint32_t*)&l23);
}

// ---------------------------------------------------------------------------
// K1: [u|v] = x @ [ (W1-W2)^T | W2^T ] — fp16 m16n8k16, 2-term split (3 MMAs).
// CTA: 64 rows x 128 cols, 8 warps; warp (rg=wid&3, cg=wid>>2):
// cg=0 -> u (fp32), cg=1 -> v (fp16). 96 MMAs/warp (was 192 tf32 k8).
// ---------------------------------------------------------------------------
#define XPITCH 68
__global__ __launch_bounds__(256, 3) void k_gemm(const float* __restrict__ x) {
    __shared__ float sX[64][XPITCH];

    int tid = threadIdx.x;
    int lane = tid & 31, wid = tid >> 5;
    int rg = wid & 3, cg = wid >> 2;

    int rowBase = blockIdx.x * 64;
    const float4* x4 = (const float4*)(x + (size_t)rowBase * 64);
    for (int i = tid; i < 64 * 16; i += 256) {
        int r = i >> 4, c4 = i & 15;
        float4 v = x4[i];
        float* p = &sX[r][c4 * 4];
        p[0] = v.x; p[1] = v.y; p[2] = v.z; p[3] = v.w;
    }
    __syncthreads();

    float acc[8][4] = {};
    int arow = rg * 16 + (lane >> 2);
    const uint2* bhBase = g_Bh + cg * 8 * 32 + lane;
    const uint2* blBase = g_Bl + cg * 8 * 32 + lane;

#pragma unroll
    for (int ks = 0; ks < 4; ks++) {
        uint32_t ah[4], al[4];
        {
            int kc = ks * 16 + (lane & 3) * 2;
            float2 p00 = *(const float2*)&sX[arow][kc];
            float2 p10 = *(const float2*)&sX[arow + 8][kc];
            float2 p01 = *(const float2*)&sX[arow][kc + 8];
            float2 p11 = *(const float2*)&sX[arow + 8][kc + 8];
            __half2 h00 = __floats2half2_rn(p00.x, p00.y);
            __half2 h10 = __floats2half2_rn(p10.x, p10.y);
            __half2 h01 = __floats2half2_rn(p01.x, p01.y);
            __half2 h11 = __floats2half2_rn(p11.x, p11.y);
            float2 f00 = __half22float2(h00), f10 = __half22float2(h10);
            float2 f01 = __half22float2(h01), f11 = __half22float2(h11);
            __half2 l00 = __floats2half2_rn(p00.x - f00.x, p00.y - f00.y);
            __half2 l10 = __floats2half2_rn(p10.x - f10.x, p10.y - f10.y);
            __half2 l01 = __floats2half2_rn(p01.x - f01.x, p01.y - f01.y);
            __half2 l11 = __floats2half2_rn(p11.x - f11.x, p11.y - f11.y);
            ah[0] = *(uint32_t*)&h00; al[0] = *(uint32_t*)&l00;
            ah[1] = *(uint32_t*)&h10; al[1] = *(uint32_t*)&l10;
            ah[2] = *(uint32_t*)&h01; al[2] = *(uint32_t*)&l01;
            ah[3] = *(uint32_t*)&h11; al[3] = *(uint32_t*)&l11;
        }
        const uint2* bh = bhBase + ks * 16 * 32;
        const uint2* bl = blBase + ks * 16 * 32;
#pragma unroll
        for (int t = 0; t < 8; t++) {
            uint2 H = __ldg(bh + t * 32);
            uint2 L = __ldg(bl + t * 32);
            mma_f16(acc[t], ah, H.x, H.y);
            mma_f16(acc[t], ah, L.x, L.y);
            mma_f16(acc[t], al, H.x, H.y);
        }
    }

    int row = rowBase + rg * 16 + (lane >> 2);
    int col = (lane & 3) * 2;
    if (cg == 0) {
#pragma unroll
        for (int t = 0; t < 8; t++) {
            *(float2*)(g_u + (size_t)row * 64 + t * 8 + col) =
                make_float2(acc[t][0], acc[t][1]);
            *(float2*)(g_u + (size_t)(row + 8) * 64 + t * 8 + col) =
                make_float2(acc[t][2], acc[t][3]);
        }
    } else {
#pragma unroll
        for (int t = 0; t < 8; t++) {
            *(__half2*)(g_vh + (size_t)row * 64 + t * 8 + col) =
                __floats2half2_rn(acc[t][0], acc[t][1]);
            *(__half2*)(g_vh + (size_t)(row + 8) * 64 + t * 8 + col) =
                __floats2half2_rn(acc[t][2], acc[t][3]);
        }
    }
}

// ---------------------------------------------------------------------------
// K2: gather (R11): smem-staged idx, fp16 v, min-skip when gamma >= 0.
// ---------------------------------------------------------------------------
__global__ __launch_bounds__(256) void k_gather(const int* __restrict__ idx) {
    __shared__ int sIdx[8][256];
    __shared__ float ssum[O_], ssq[O_];

    int tid  = threadIdx.x;
    int lane = tid & 31;
    int half = lane >> 4;
    int c4   = lane & 15;
    int w    = tid >> 5;
    int warpId = blockIdx.x * 8 + w;
    int pbase  = warpId * 16;
    int b = pbase >> 14;
    const uint2* vb = (const uint2*)(g_vh + (size_t)b * N_ * O_);

    {
        const int4* src = (const int4*)(idx + (size_t)pbase * K_);
        ((int4*)sIdx[w])[lane]      = src[lane];
        ((int4*)sIdx[w])[lane + 32] = src[lane + 32];
    }
    __syncwarp();

    const int gneg = g_gneg;

    float4 cs1 = {0, 0, 0, 0}, cs2 = {0, 0, 0, 0};

    for (int p = 0; p < 16; ++p) {
        int point = pbase + p;
        const int* sip = &sIdx[w][p * 16];

        float4 u = __ldg((const float4*)(g_u + (size_t)point * O_) + c4);

        float4 mx = make_float4(-3.4e38f, -3.4e38f, -3.4e38f, -3.4e38f);
        float4 mn = make_float4( 3.4e38f,  3.4e38f,  3.4e38f,  3.4e38f);
        float4 s1 = {0, 0, 0, 0}, s2 = {0, 0, 0, 0};

        int j[8];
#pragma unroll
        for (int s = 0; s < 8; s++) j[s] = sip[2 * s + half];

        if (!gneg) {
#pragma unroll
            for (int s = 0; s < 8; s++) {
                uint2 raw = __ldg(vb + (size_t)j[s] * 16 + c4);
                float2 v01 = __half22float2(*(__half2*)&raw.x);
                float2 v23 = __half22float2(*(__half2*)&raw.y);
                mx.x = fmaxf(mx.x, v01.x); s1.x += v01.x; s2.x = fmaf(v01.x, v01.x, s2.x);
                mx.y = fmaxf(mx.y, v01.y); s1.y += v01.y; s2.y = fmaf(v01.y, v01.y, s2.y);
                mx.z = fmaxf(mx.z, v23.x); s1.z += v23.x; s2.z = fmaf(v23.x, v23.x, s2.z);
                mx.w = fmaxf(mx.w, v23.y); s1.w += v23.y; s2.w = fmaf(v23.y, v23.y, s2.w);
            }
        } else {
#pragma unroll
            for (int s = 0; s < 8; s++) {
                uint2 raw = __ldg(vb + (size_t)j[s] * 16 + c4);
                float2 v01 = __half22float2(*(__half2*)&raw.x);
                float2 v23 = __half22float2(*(__half2*)&raw.y);
                mx.x = fmaxf(mx.x, v01.x); mn.x = fminf(mn.x, v01.x); s1.x += v01.x; s2.x = fmaf(v01.x, v01.x, s2.x);
                mx.y = fmaxf(mx.y, v01.y); mn.y = fminf(mn.y, v01.y); s1.y += v01.y; s2.y = fmaf(v01.y, v01.y, s2.y);
                mx.z = fmaxf(mx.z, v23.x); mn.z = fminf(mn.z, v23.x); s1.z += v23.x; s2.z = fmaf(v23.x, v23.x, s2.z);
                mx.w = fmaxf(mx.w, v23.y); mn.w = fminf(mn.w, v23.y); s1.w += v23.y; s2.w = fmaf(v23.y, v23.y, s2.w);
            }
        }

        mx.x = fmaxf(mx.x, __shfl_xor_sync(0xffffffffu, mx.x, 16));
        mx.y = fmaxf(mx.y, __shfl_xor_sync(0xffffffffu, mx.y, 16));
        mx.z = fmaxf(mx.z, __shfl_xor_sync(0xffffffffu, mx.z, 16));
        mx.w = fmaxf(mx.w, __shfl_xor_sync(0xffffffffu, mx.w, 16));
        if (half == 0) {
            ((float4*)(g_mx + (size_t)point * O_))[c4] =
                make_float4(u.x + mx.x, u.y + mx.y, u.z + mx.z, u.w + mx.w);
        }
        if (gneg) {
            mn.x = fminf(mn.x, __shfl_xor_sync(0xffffffffu, mn.x, 16));
            mn.y = fminf(mn.y, __shfl_xor_sync(0xffffffffu, mn.y, 16));
            mn.z = fminf(mn.z, __shfl_xor_sync(0xffffffffu, mn.z, 16));
            mn.w = fminf(mn.w, __shfl_xor_sync(0xffffffffu, mn.w, 16));
            if (half == 0) {
                ((float4*)(g_mn + (size_t)point * O_))[c4] =
                    make_float4(u.x + mn.x, u.y + mn.y, u.z + mn.z, u.w + mn.w);
            }
        }

        cs1.x += 8.f * u.x + s1.x;  cs2.x += fmaf(8.f * u.x, u.x, fmaf(2.f * u.x, s1.x, s2.x));
        cs1.y += 8.f * u.y + s1.y;  cs2.y += fmaf(8.f * u.y, u.y, fmaf(2.f * u.y, s1.y, s2.y));
        cs1.z += 8.f * u.z + s1.z;  cs2.z += fmaf(8.f * u.z, u.z, fmaf(2.f * u.z, s1.z, s2.z));
        cs1.w += 8.f * u.w + s1.w;  cs2.w += fmaf(8.f * u.w, u.w, fmaf(2.f * u.w, s1.w, s2.w));
    }

    if (tid < O_) { ssum[tid] = 0.f; ssq[tid] = 0.f; }
    __syncthreads();
    int cb = c4 * 4;
    atomicAdd(&ssum[cb + 0], cs1.x); atomicAdd(&ssq[cb + 0], cs2.x);
    atomicAdd(&ssum[cb + 1], cs1.y); atomicAdd(&ssq[cb + 1], cs2.y);
    atomicAdd(&ssum[cb + 2], cs1.z); atomicAdd(&ssq[cb + 2], cs2.z);
    atomicAdd(&ssum[cb + 3], cs1.w); atomicAdd(&ssq[cb + 3], cs2.w);
    __syncthreads();
    if (tid < O_) {
        atomicAdd(&g_sum[tid], ssum[tid]);
        atomicAdd(&g_sq[tid],  ssq[tid]);
    }
}

// ---------------------------------------------------------------------------
// K3: fused stats + epilogue; 4 float4 per thread (amortized prologue).
// ---------------------------------------------------------------------------
#define OUT_ITERS 4
#define OUT_STEP  (1024 * 256)     // grid * block, in float4 units
__global__ __launch_bounds__(256) void k_out(const float* __restrict__ gamma,
                                             const float* __restrict__ beta,
                                             float* __restrict__ out) {
    __shared__ __align__(16) float sc[O_];
    __shared__ __align__(16) float sh[O_];
    int tid = threadIdx.x;
    if (tid < O_) {
        float inv  = 1.0f / TOTSAMP;
        float mean = g_sum[tid] * inv;
        float var  = g_sq[tid] * inv - mean * mean;
        float s    = rsqrtf(var + BN_EPS) * gamma[tid];
        sc[tid] = s;
        sh[tid] = beta[tid] - mean * s;
    }
    __syncthreads();

    size_t base = (size_t)blockIdx.x * 256 + tid;
    int o4 = (int)(base & 15);          // channel group is invariant across steps
    float4 s4 = ((const float4*)sc)[o4];
    float4 b4 = ((const float4*)sh)[o4];
    int gneg = g_gneg;

#pragma unroll
    for (int it = 0; it < OUT_ITERS; it++) {
        size_t i4 = base + (size_t)it * OUT_STEP;
        float4 m;
        if (!gneg) {
            m = __ldg((const float4*)g_mx + i4);
        } else {
            float4 a = __ldg((const float4*)g_mx + i4);
            float4 c = __ldg((const float4*)g_mn + i4);
            m.x = (s4.x >= 0.f) ? a.x : c.x;
            m.y = (s4.y >= 0.f) ? a.y : c.y;
            m.z = (s4.z >= 0.f) ? a.z : c.z;
            m.w = (s4.w >= 0.f) ? a.w : c.w;
        }
        float4 r;
        r.x = fmaxf(fmaf(m.x, s4.x, b4.x), 0.f);
        r.y = fmaxf(fmaf(m.y, s4.y, b4.y), 0.f);
        r.z = fmaxf(fmaf(m.z, s4.z, b4.z), 0.f);
        r.w = fmaxf(fmaf(m.w, s4.w, b4.w), 0.f);
        ((float4*)out)[i4] = r;
    }
}

extern "C" void kernel_launch(void* const* d_in, const int* in_sizes, int n_in,
                              void* d_out, int out_size) {
    const float* x     = (const float*)d_in[0];
    const int*   idx   = (const int*)  d_in[1];
    const float* w     = (const float*)d_in[2];
    const float* gamma = (const float*)d_in[3];
    const float* beta  = (const float*)d_in[4];
    float* out = (float*)d_out;

    k_prep  <<<8, 256>>>(w, gamma);
    k_gemm  <<<RTOT / 64, 256>>>(x);
    k_gather<<<RTOT / (8 * 16), 256>>>(idx);
    k_out   <<<1024, 256>>>(gamma, beta, out);
}